// round 6
// baseline (speedup 1.0000x reference)
#include <cuda_runtime.h>
#include <cuda_fp16.h>

#define BB 2
#define CC 32
#define HH 128
#define WW 416
#define DD 48
#define HW_ (HH*WW)
#define CHW_ (CC*HH*WW)
#define ISCALE 0.05892556509887896f  // 1/sqrt(C*K2) = 1/sqrt(288)

// Emulate the reference's fp16 cast, stored as float32.
__device__ __forceinline__ float h16(float v) {
    return __half2float(__float2half_rn(v));
}

// Device-global scratch (allocation forbidden)
__device__ float g_Al[BB*CHW_];     // normalized 3x3 box sum of xl: box/max(||patch||,eps)
__device__ float g_Br[BB*CHW_];     // normalized 3x3 box sum of xr
__device__ float g_nli[BB*HW_];     // 1/max(||patch_l||, eps)
__device__ float g_nri[BB*HW_];
__device__ float g_Grow[BB*DD*HW_]; // horizontal 3-tap of G_{2d} per row

// ---------------------------------------------------------------------------
// Kernel 1: pre-normalized box sums + patch norms. Shuffle-based horizontal
// 3-tap; no smem, no barriers. Warps cover 30 output columns each.
// ---------------------------------------------------------------------------
__global__ __launch_bounds__(448) void cv_prep_kernel(
    const float* __restrict__ xl, const float* __restrict__ xr)
{
    const int t    = threadIdx.x;
    const int wi   = t >> 5;
    const int lane = t & 31;
    const int h    = blockIdx.x;
    const int b    = blockIdx.y;
    const int img  = blockIdx.z;
    const float* x = img ? xr : xl;
    float* gbox    = img ? g_Br : g_Al;
    float* gn      = img ? g_nri : g_nli;

    const int u = wi*30 + lane - 1;          // -1 .. 419
    const bool vu = (u >= 0) && (u < WW);
    const bool h0 = (h > 0), h1 = (h < HH - 1);
    const float* base = x + b*CHW_ + h*WW + (vu ? u : 0);

    float ssum = 0.f;
    float boxv[CC];
    #pragma unroll
    for (int c = 0; c < CC; c++) {
        float r0 = (vu && h0) ? __ldg(base + c*HW_ - WW) : 0.f;
        float r1 =  vu        ? __ldg(base + c*HW_)      : 0.f;
        float r2 = (vu && h1) ? __ldg(base + c*HW_ + WW) : 0.f;
        float cs = r0 + r1 + r2;
        ssum += r0*r0 + r1*r1 + r2*r2;
        float csl = __shfl_up_sync(0xffffffffu, cs, 1);
        float csr = __shfl_down_sync(0xffffffffu, cs, 1);
        boxv[c] = csl + cs + csr;
    }
    float sql = __shfl_up_sync(0xffffffffu, ssum, 1);
    float sqr = __shfl_down_sync(0xffffffffu, ssum, 1);
    float ni = 1.f / fmaxf(sqrtf(sql + ssum + sqr), 1e-3f);

    if (lane >= 1 && lane <= 30 && u < WW) {   // u >= 0 guaranteed (lane>=1)
        float* ob = gbox + b*CHW_ + h*WW + u;
        #pragma unroll
        for (int c = 0; c < CC; c++) ob[c*HW_] = boxv[c] * ni;
        gn[b*HW_ + h*WW + u] = ni;
    }
}

// ---------------------------------------------------------------------------
// Kernel 2: L and R channels, fp16-paired smem, 2 disparities per LDS.32.
// ---------------------------------------------------------------------------
#define SJ 176   // Al words: j -> {A'[u0+j], A'[u0+j+1]}
#define BJ 180   // Br words: j -> {B'[u0-48+j], B'[u0-48+j-1]}

__global__ __launch_bounds__(128) void cv_lrcost_kernel(
    const float* __restrict__ xm, float* __restrict__ out)
{
    __shared__ __half2 s_Al2[CC*SJ];   // 22528 B
    __shared__ __half2 s_Br2[CC*BJ];   // 23040 B

    const int t  = threadIdx.x;
    const int u0 = blockIdx.x * 128;
    const int h  = blockIdx.y;
    const int b  = blockIdx.z;
    const int grow = b*CHW_ + h*WW;

    // Al fill: words {A'[col+k], A'[col+k+1]}
    for (int i = t; i < CC*44; i += 128) {
        int c = i / 44, q = i % 44;
        int col = u0 + 4*q;
        float4 a4 = make_float4(0.f,0.f,0.f,0.f);
        if (col <= WW-4) a4 = *(const float4*)(g_Al + grow + c*HW_ + col);
        float a5 = (col+4 < WW) ? __ldg(g_Al + grow + c*HW_ + col + 4) : 0.f;
        __half2* dst = s_Al2 + c*SJ + 4*q;
        dst[0] = __floats2half2_rn(a4.x, a4.y);
        dst[1] = __floats2half2_rn(a4.y, a4.z);
        dst[2] = __floats2half2_rn(a4.z, a4.w);
        dst[3] = __floats2half2_rn(a4.w, a5);
    }
    // Br fill: words {B'[col+k], B'[col+k-1]}
    for (int i = t; i < CC*45; i += 128) {
        int c = i / 45, q = i % 45;
        int col = u0 - 48 + 4*q;
        float4 b4 = make_float4(0.f,0.f,0.f,0.f);
        if (col >= 0 && col <= WW-4) b4 = *(const float4*)(g_Br + grow + c*HW_ + col);
        float bm1 = (col-1 >= 0 && col-1 < WW) ? __ldg(g_Br + grow + c*HW_ + col - 1) : 0.f;
        __half2* dst = s_Br2 + c*BJ + 4*q;
        dst[0] = __floats2half2_rn(b4.x, bm1);
        dst[1] = __floats2half2_rn(b4.y, b4.x);
        dst[2] = __floats2half2_rn(b4.z, b4.y);
        dst[3] = __floats2half2_rn(b4.w, b4.z);
    }
    __syncthreads();

    const int w = u0 + t;
    if (w >= WW) return;

    float f[CC];
    {
        float ss = 0.f;
        const float* pm = xm + b*CHW_ + h*WW + w;
        #pragma unroll
        for (int c = 0; c < CC; c++) {
            float v = __ldg(pm + c*HW_);
            f[c] = v; ss += v*v;
        }
        float nf = ISCALE / fmaxf(sqrtf(ss), 1e-3f);
        #pragma unroll
        for (int c = 0; c < CC; c++) f[c] *= nf;
    }

    int ob = (b*3)*DD*HW_ + h*WW + w;   // channel-L base at d=0
    for (int dp = 0; dp < 24; dp++) {
        const int jA = t + 2*dp;         // [0,173]
        const int jB = t - 2*dp + 48;    // [2,175]
        float aL0 = 0.f, aL1 = 0.f, aR0 = 0.f, aR1 = 0.f;
        #pragma unroll
        for (int c = 0; c < CC; c++) {
            float2 av = __half22float2(s_Al2[c*SJ + jA]);
            aL0 += f[c] * av.x;
            aL1 += f[c] * av.y;
            float2 bv = __half22float2(s_Br2[c*BJ + jB]);
            aR0 += f[c] * bv.x;
            aR1 += f[c] * bv.y;
        }
        int o = ob + 2*dp*HW_;
        out[o]               = h16(fminf(fmaxf(aL0, -10.f), 10.f));
        out[o + HW_]         = h16(fminf(fmaxf(aL1, -10.f), 10.f));
        out[o + DD*HW_]      = h16(fminf(fmaxf(aR0, -10.f), 10.f));
        out[o + (DD+1)*HW_]  = h16(fminf(fmaxf(aR1, -10.f), 10.f));
    }
}

// ---------------------------------------------------------------------------
// Kernel 3: Grow(d,r,o) = horizontal 3-tap of G_{2d}(r,u)=dot_c(xl[u],xr[u-2d]).
// fp16-paired smem (2 disparities per LDS.32), warp-shuffle 3-tap, no
// per-d barriers. Warps overlap by 2 lanes (30 outputs each).
// ---------------------------------------------------------------------------
#define XRW 308   // words k -> {xr[lo+k], xr[lo+k-2]}, lo = u0-96

__global__ __launch_bounds__(224) void cv_g_kernel(
    const float* __restrict__ xl,
    const float* __restrict__ xr)
{
    __shared__ __half2 s_xr2[CC*XRW];   // 39424 B

    const int t    = threadIdx.x;
    const int wi   = t >> 5;
    const int lane = t & 31;
    const int u0   = blockIdx.x * 208;
    const int r    = blockIdx.y;
    const int b    = blockIdx.z;
    const int lo   = u0 - 96;
    const int rbase = b*CHW_ + r*WW;

    for (int i = t; i < CC*77; i += 224) {
        int c = i / 77, q = i % 77;
        int col = lo + 4*q;
        float4 f4 = make_float4(0.f,0.f,0.f,0.f);
        if (col >= 0 && col <= WW-4) f4 = *(const float4*)(xr + rbase + c*HW_ + col);
        float m2 = (col-2 >= 0 && col-2 < WW) ? __ldg(xr + rbase + c*HW_ + col - 2) : 0.f;
        float m1 = (col-1 >= 0 && col-1 < WW) ? __ldg(xr + rbase + c*HW_ + col - 1) : 0.f;
        __half2* dst = s_xr2 + c*XRW + 4*q;
        dst[0] = __floats2half2_rn(f4.x, m2);
        dst[1] = __floats2half2_rn(f4.y, m1);
        dst[2] = __floats2half2_rn(f4.z, f4.x);
        dst[3] = __floats2half2_rn(f4.w, f4.y);
    }
    __syncthreads();

    const int u = u0 - 1 + wi*30 + lane;     // g column this lane computes
    const bool vu = (u >= 0) && (u < WW);
    float rl[CC];
    #pragma unroll
    for (int c = 0; c < CC; c++)
        rl[c] = vu ? __ldg(xl + rbase + c*HW_ + u) : 0.f;

    const bool wr = (lane >= 1) && (lane <= 30) && (u <= u0 + 207) && (u < WW);
    const int obase = b*DD*HW_ + r*WW + (wr ? u : 0);

    for (int dp = 0; dp < 24; dp++) {
        int k = (u - u0) + 96 - 4*dp;        // in [3,305]
        float g0 = 0.f, g1 = 0.f;
        #pragma unroll
        for (int c = 0; c < CC; c++) {
            float2 v = __half22float2(s_xr2[c*XRW + k]);
            g0 += rl[c] * v.x;               // disparity 2dp
            g1 += rl[c] * v.y;               // disparity 2dp+1
        }
        float s0 = g0 + __shfl_up_sync(0xffffffffu, g0, 1)
                      + __shfl_down_sync(0xffffffffu, g0, 1);
        float s1 = g1 + __shfl_up_sync(0xffffffffu, g1, 1)
                      + __shfl_down_sync(0xffffffffu, g1, 1);
        if (wr) {
            g_Grow[obase + (2*dp)*HW_]   = s0;
            g_Grow[obase + (2*dp+1)*HW_] = s1;
        }
    }
}

// ---------------------------------------------------------------------------
// Kernel 4: LR channel -- vertical 3-tap over Grow + normalization.
// ---------------------------------------------------------------------------
__global__ __launch_bounds__(416) void cv_lr_out_kernel(float* __restrict__ out)
{
    const int w = threadIdx.x;
    const int h = blockIdx.x;
    const int d = blockIdx.y;
    const int b = blockIdx.z;

    float val = 0.f;
    if (w >= d && w < WW - d) {
        int u = w + d;
        const float* gb = g_Grow + (b*DD + d)*HW_ + u;
        float s = __ldg(gb + h*WW);
        if (h > 0)      s += __ldg(gb + (h-1)*WW);
        if (h < HH - 1) s += __ldg(gb + (h+1)*WW);
        float ni = __ldg(g_nli + b*HW_ + h*WW + u);
        float nr = __ldg(g_nri + b*HW_ + h*WW + (w - d));
        val = fminf(fmaxf(s * ni * nr * ISCALE, -10.f), 10.f);
    }
    out[(b*3 + 2)*DD*HW_ + d*HW_ + h*WW + w] = h16(val);
}

// ---------------------------------------------------------------------------
extern "C" void kernel_launch(void* const* d_in, const int* in_sizes, int n_in,
                              void* d_out, int out_size)
{
    const float* xl = (const float*)d_in[0];
    const float* xm = (const float*)d_in[1];
    const float* xr = (const float*)d_in[2];
    float* out = (float*)d_out;

    cv_prep_kernel<<<dim3(HH, BB, 2), 448>>>(xl, xr);
    cv_g_kernel<<<dim3(2, HH, BB), 224>>>(xl, xr);
    cv_lrcost_kernel<<<dim3(4, HH, BB), 128>>>(xm, out);
    cv_lr_out_kernel<<<dim3(HH, DD, BB), 416>>>(out);
}